// round 16
// baseline (speedup 1.0000x reference)
#include <cuda_runtime.h>
#include <cstdint>

#define N1 16384
#define N2 16384
#define GRID 128
#define NCELL (GRID * GRID)
#define RLO (-6.0f)
#define RANGE 12.0f
#define CELLW (RANGE / (float)GRID)      // 0.09375, exact in fp32
#define INVCELL ((float)GRID / RANGE)
#define QBLOCKS 512
#define QTHREADS 128
#define GSZ 4                            // lanes per query (fast path)
#define FINF __uint_as_float(0x7f800000u)

// Cell counts: zero at kernel entry (static zero init; scan_scatter re-zeroes
// after consuming -> replay invariant).
__device__ int g_cnt[NCELL];
// After scan: exclusive prefix. After scatter: inclusive end per cell.
// start(c) = (c>0) ? g_ofs[c-1] : 0.  Rewritten fresh every launch.
__device__ int g_ofs[NCELL];
__device__ float2 g_spts[N2];
__device__ float g_bsum[QBLOCKS];
__device__ unsigned int g_done = 0;

__device__ __forceinline__ int clampi(int v, int lo, int hi) {
    return max(lo, min(hi, v));
}

__device__ __forceinline__ int cell_of(float x, float y) {
    int ix = clampi((int)((x - RLO) * INVCELL), 0, GRID - 1);
    int iy = clampi((int)((y - RLO) * INVCELL), 0, GRID - 1);
    return iy * GRID + ix;
}

// ── Kernel 1: count ──────────────────────────────────────────────────────────
__global__ __launch_bounds__(256)
void count_kernel(const float2* __restrict__ pos2) {
    int i = blockIdx.x * 256 + threadIdx.x;
    float2 p = pos2[i];
    atomicAdd(&g_cnt[cell_of(p.x, p.y)], 1);
}

// ── Kernel 2: scan (int4-vectorized) + scatter, one block ────────────────────
__global__ __launch_bounds__(1024)
void scan_scatter_kernel(const float2* __restrict__ pos2) {
    __shared__ int sc[1024];
    const int t = threadIdx.x;
    const int4* cv = (const int4*)&g_cnt[t * 16];
    int4 c[4];
    int loc[16];
    int s = 0;
#pragma unroll
    for (int k = 0; k < 4; k++) c[k] = cv[k];
#pragma unroll
    for (int k = 0; k < 4; k++) {
        loc[4 * k + 0] = s; s += c[k].x;
        loc[4 * k + 1] = s; s += c[k].y;
        loc[4 * k + 2] = s; s += c[k].z;
        loc[4 * k + 3] = s; s += c[k].w;
    }
    sc[t] = s;
    __syncthreads();
    for (int off = 1; off < 1024; off <<= 1) {
        int v = (t >= off) ? sc[t - off] : 0;
        __syncthreads();
        sc[t] += v;
        __syncthreads();
    }
    int excl = sc[t] - s;
    int4* ov = (int4*)&g_ofs[t * 16];
    int4* zv = (int4*)&g_cnt[t * 16];
    const int4 zero = make_int4(0, 0, 0, 0);
#pragma unroll
    for (int k = 0; k < 4; k++) {
        ov[k] = make_int4(excl + loc[4 * k + 0], excl + loc[4 * k + 1],
                          excl + loc[4 * k + 2], excl + loc[4 * k + 3]);
        zv[k] = zero;                    // restore zero invariant for replay
    }
    __syncthreads();

    // Scatter: 16 points per thread (atomicAdd turns g_ofs into inclusive ends)
#pragma unroll
    for (int k = 0; k < N2 / 1024; k++) {
        int i = t + k * 1024;
        float2 p = pos2[i];
        int c = cell_of(p.x, p.y);
        int pos = atomicAdd(&g_ofs[c], 1);
        g_spts[pos] = p;
    }
}

// Scan points [s,e) with this lane's stride-GSZ subset. No collective ops.
__device__ __forceinline__ void scan_pts_strided(int s, int e, int sub,
                                                 float qx, float qy, float& m) {
    for (int i = s + sub; i < e; i += GSZ) {
        float2 p = g_spts[i];
        float dx = qx - p.x;
        float dy = qy - p.y;
        m = fminf(m, fmaf(dx, dx, dy * dy));
    }
}

// Scan ALL points in [s,e).
__device__ __forceinline__ void scan_pts_all(int s, int e,
                                             float qx, float qy, float& m) {
    for (int i = s; i < e; i++) {
        float2 p = g_spts[i];
        float dx = qx - p.x;
        float dy = qy - p.y;
        m = fminf(m, fmaf(dx, dx, dy * dy));
    }
}

// Min across the 4 lanes of each group (all 32 lanes execute).
__device__ __forceinline__ float lane_combine(float m) {
    m = fminf(m, __shfl_xor_sync(0xffffffffu, m, 1));
    m = fminf(m, __shfl_xor_sync(0xffffffffu, m, 2));
    return m;
}

// Min across all 32 lanes (all lanes execute).
__device__ __forceinline__ float warp_combine(float m) {
    m = fminf(m, __shfl_xor_sync(0xffffffffu, m, 1));
    m = fminf(m, __shfl_xor_sync(0xffffffffu, m, 2));
    m = fminf(m, __shfl_xor_sync(0xffffffffu, m, 4));
    m = fminf(m, __shfl_xor_sync(0xffffffffu, m, 8));
    m = fminf(m, __shfl_xor_sync(0xffffffffu, m, 16));
    return m;
}

// ── Kernel 3: query (4 lanes/query fast path, warp-coop fallback) + mean ─────
__global__ __launch_bounds__(QTHREADS)
void query_kernel(const float2* __restrict__ pos1, float* __restrict__ out) {
    __shared__ float red[QTHREADS];
    __shared__ unsigned int s_last;
    const int tid  = threadIdx.x;
    const int lane = tid & 31;
    const int gtid = blockIdx.x * QTHREADS + tid;
    const int q    = gtid >> 2;
    const int sub  = gtid & (GSZ - 1);

    float2 qp = pos1[q];
    int ix = clampi((int)((qp.x - RLO) * INVCELL), 0, GRID - 1);
    int iy = clampi((int)((qp.y - RLO) * INVCELL), 0, GRID - 1);

    float m = FINF;

    // Fast path: 3x3 neighborhood; 6 range offsets loaded up front (batched).
    int x0 = max(ix - 1, 0), x1 = min(ix + 1, GRID - 1);
    int y0 = max(iy - 1, 0), y1 = min(iy + 1, GRID - 1);
    int nrows = y1 - y0 + 1;
    int rs[3], re[3];
#pragma unroll
    for (int k = 0; k < 3; k++) {
        int yy = min(y0 + k, y1);
        int c0 = yy * GRID + x0;
        rs[k] = (c0 > 0) ? g_ofs[c0 - 1] : 0;
        re[k] = g_ofs[yy * GRID + x1];
    }
#pragma unroll
    for (int k = 0; k < 3; k++) {
        if (k < nrows) scan_pts_strided(rs[k], re[k], sub, qp.x, qp.y, m);
    }

    m = lane_combine(m);   // group min; all 32 lanes participate

    // Exact bound for the scanned rect (domain-border sides -> inf).
    float bx0 = (x0 == 0)        ? FINF : qp.x - (RLO + (float)x0 * CELLW);
    float bx1 = (x1 == GRID - 1) ? FINF : (RLO + (float)(x1 + 1) * CELLW) - qp.x;
    float by0 = (y0 == 0)        ? FINF : qp.y - (RLO + (float)y0 * CELLW);
    float by1 = (y1 == GRID - 1) ? FINF : (RLO + (float)(y1 + 1) * CELLW) - qp.y;
    float b = fminf(fminf(bx0, bx1), fminf(by0, by1));

    // Warp-cooperative fallback: ~1% of queries have b^2 < m. The ballot mask
    // is warp-uniform, so the whole warp walks the needy groups together; all
    // collectives below are full-mask and executed by all 32 lanes.
    unsigned int need = __ballot_sync(0xffffffffu, b * b < m);
    while (need) {
        int glead = (__ffs(need) - 1) & ~3;          // leader lane of the group
        need &= ~(0xFu << glead);
        float cqx = __shfl_sync(0xffffffffu, qp.x, glead);
        float cqy = __shfl_sync(0xffffffffu, qp.y, glead);
        int   cix = __shfl_sync(0xffffffffu, ix,   glead);
        int   ciy = __shfl_sync(0xffffffffu, iy,   glead);
        float cm  = __shfl_sync(0xffffffffu, m,    glead);

        // Geometrically-doubling squares; rows distributed across 32 lanes.
        // R=GRID covers the whole grid (bound -> inf) => guaranteed exit.
        for (int R = 2; R <= GRID; R <<= 1) {
            int xa = max(cix - R, 0), xb = min(cix + R, GRID - 1);
            int ya = max(ciy - R, 0), yb = min(ciy + R, GRID - 1);
            float lm = cm;
            for (int yy = ya + lane; yy <= yb; yy += 32) {
                int c0 = yy * GRID + xa;
                int ss = (c0 > 0) ? g_ofs[c0 - 1] : 0;
                int ee = g_ofs[yy * GRID + xb];
                scan_pts_all(ss, ee, cqx, cqy, lm);
            }
            cm = warp_combine(lm);
            float sx0 = (xa == 0)        ? FINF : cqx - (RLO + (float)xa * CELLW);
            float sx1 = (xb == GRID - 1) ? FINF : (RLO + (float)(xb + 1) * CELLW) - cqx;
            float sy0 = (ya == 0)        ? FINF : cqy - (RLO + (float)ya * CELLW);
            float sy1 = (yb == GRID - 1) ? FINF : (RLO + (float)(yb + 1) * CELLW) - cqy;
            float sb = fminf(fminf(sx0, sx1), fminf(sy0, sy1));
            if (sb * sb >= cm) break;    // warp-uniform (cm, sb identical)
        }
        if ((lane & ~3) == glead) m = cm;   // hand result back to the group
    }

    red[tid] = (sub == 0) ? sqrtf(m) : 0.0f;
    __syncthreads();
    for (int w = QTHREADS / 2; w > 0; w >>= 1) {
        if (tid < w) red[tid] += red[tid + w];
        __syncthreads();
    }
    if (tid == 0) g_bsum[blockIdx.x] = red[0];

    // Done-counter tail: last block computes the mean (fixed order -> determ.)
    __threadfence();
    __syncthreads();
    if (tid == 0) {
        unsigned int prev = atomicAdd(&g_done, 1u);
        s_last = (prev == (unsigned int)(QBLOCKS - 1)) ? 1u : 0u;
    }
    __syncthreads();
    if (s_last) {
        __threadfence();
        float s = 0.0f;
#pragma unroll
        for (int k = 0; k < QBLOCKS / QTHREADS; k++) {
            s += __ldcg(&g_bsum[tid + k * QTHREADS]);
        }
        red[tid] = s;
        __syncthreads();
        for (int w = QTHREADS / 2; w > 0; w >>= 1) {
            if (tid < w) red[tid] += red[tid + w];
            __syncthreads();
        }
        if (tid == 0) {
            out[0] = red[0] * (1.0f / (float)N1);
            g_done = 0;   // reset for next replay
        }
    }
}

extern "C" void kernel_launch(void* const* d_in, const int* in_sizes, int n_in,
                              void* d_out, int out_size) {
    const float2* pos1 = (const float2*)d_in[0];
    const float2* pos2 = (const float2*)d_in[1];
    float* out = (float*)d_out;

    count_kernel<<<N2 / 256, 256>>>(pos2);
    scan_scatter_kernel<<<1, 1024>>>(pos2);
    query_kernel<<<QBLOCKS, QTHREADS>>>(pos1, out);
}